// round 1
// baseline (speedup 1.0000x reference)
#include <cuda_runtime.h>
#include <cstdint>

// ---------------------------------------------------------------------------
// CMAFM block, fully fused: one CTA per 8x8 window. All intermediates in smem.
// B=4, C=128, H=W=256, WS=8 -> 4096 windows. 256 threads/CTA.
// ---------------------------------------------------------------------------

#define TB 256

constexpr int CC    = 128;        // channels
constexpr int HH    = 256;
constexpr int WWI   = 256;
constexpr int NPIX  = 64;         // pixels per window
constexpr int XP    = 132;        // smem row pitch (floats), mult of 4, conflict-tuned
constexpr int WP128 = 132;        // weight stage pitch for Cin=128
constexpr int WP256 = 260;        // weight stage pitch for Cin=256
constexpr int NCH   = 16;         // output channels per GEMM chunk
constexpr int BUF   = NPIX * XP;  // 8448 floats per buffer
constexpr int SMEM_FLOATS = 6 * BUF + NCH * WP256;  // 50688 + 4160 = 54848
// smem bytes = 219392 (< 227KB opt-in limit)
constexpr size_t NTOT = 4ull * 128 * 256 * 256;     // 33,554,432 elems per tensor

struct P {
    const float *F_opt, *F_sar;
    const float *wq_opt, *bq_opt, *wk_opt, *bk_opt, *wv_opt, *bv_opt;
    const float *wq_sar, *bq_sar, *wk_sar, *bk_sar, *wv_sar, *bv_sar;
    const float *pw_o2s, *pb_o2s, *pw_s2o, *pb_s2o;
    const float *gow, *gob, *gsw, *gsb;
    const float *fw, *fb;
    const float *gma, *bta, *mu, *var;
    float *out;
};

// ---------------------------------------------------------------------------
// Load one window (64 px x 128 ch) from NCHW global into smem [n][c], n=i*8+j.
// tid -> (c = tid/2, q = tid&1); each thread loads 8 float4 (coalesced 32B pairs).
// ---------------------------------------------------------------------------
__device__ __forceinline__ void load_window(float* dst, const float* __restrict__ src,
                                            int gbase, int tid) {
    const int c = tid >> 1, qq = tid & 1;
    const float* s = src + gbase + c * (HH * WWI) + qq * 4;
#pragma unroll
    for (int i = 0; i < 8; ++i) {
        float4 v = *(const float4*)(s + i * WWI);
        float* d = dst + (i * 8 + qq * 4) * XP + c;
        d[0] = v.x; d[XP] = v.y; d[2 * XP] = v.z; d[3 * XP] = v.w;
    }
}

// Transposed store: smem [n][c] -> NCHW global.
__device__ __forceinline__ void store_window(float* __restrict__ g, const float* sbuf,
                                             int gbase, int tid) {
    const int c = tid >> 1, qq = tid & 1;
    float* gp = g + gbase + c * (HH * WWI) + qq * 4;
    const float* sp0 = sbuf + qq * 4 * XP + c;
#pragma unroll
    for (int i = 0; i < 8; ++i) {
        const float* sp = sp0 + i * 8 * XP;
        *(float4*)(gp + i * WWI) = make_float4(sp[0], sp[XP], sp[2 * XP], sp[3 * XP]);
    }
}

// ---------------------------------------------------------------------------
// GEMM: out[64][128] = X[64][CIN] @ W^T + bias, W row-major [128][CIN] global.
// Processed in 8 chunks of 16 out-channels; each chunk's weights staged in smem.
// Per-thread 2x2 micro-tile: rows {rg, rg+32}, cols {c0, c0+1}.
// Lane map chosen for conflict-free smem float4 reads (X: rg_l*4 banks distinct,
// W: cg_l*8 banks distinct at pitch 132/260).
// For CIN=256 the input is the concat [x0 | x1] along channels.
// ---------------------------------------------------------------------------
template <int CIN>
__device__ __noinline__ void gemm(const float* __restrict__ Wg,
                                  const float* __restrict__ bias,
                                  const float* __restrict__ x0,
                                  const float* __restrict__ x1,
                                  float* __restrict__ outb,
                                  float* __restrict__ wst) {
    const int tid = threadIdx.x;
    constexpr int WPI = (CIN == 128) ? WP128 : WP256;
    const int L  = tid & 31, w = tid >> 5;
    const int rg = (L & 7) + (w & 3) * 8;          // 0..31
    const int cg = ((L >> 3) & 3) + (w >> 2) * 4;  // 0..7

    for (int ch = 0; ch < 8; ++ch) {
        // stage 16 x CIN weights (coalesced global -> padded smem)
        for (int idx = tid * 4; idx < NCH * CIN; idx += TB * 4) {
            const int r = idx / CIN, c = idx % CIN;
            float4 v = *(const float4*)(Wg + ch * (NCH * CIN) + idx);
            *(float4*)(wst + r * WPI + c) = v;
        }
        __syncthreads();

        const float* wr0 = wst + (cg * 2) * WPI;
        const float* wr1 = wr0 + WPI;
        float a00 = 0.f, a01 = 0.f, a10 = 0.f, a11 = 0.f;

        const float* xr0 = x0 + rg * XP;
        const float* xr1 = x0 + (rg + 32) * XP;
#pragma unroll 8
        for (int ci = 0; ci < 128; ci += 4) {
            float4 xa = *(const float4*)(xr0 + ci);
            float4 xb = *(const float4*)(xr1 + ci);
            float4 wa = *(const float4*)(wr0 + ci);
            float4 wb = *(const float4*)(wr1 + ci);
            a00 += xa.x * wa.x; a00 += xa.y * wa.y; a00 += xa.z * wa.z; a00 += xa.w * wa.w;
            a01 += xa.x * wb.x; a01 += xa.y * wb.y; a01 += xa.z * wb.z; a01 += xa.w * wb.w;
            a10 += xb.x * wa.x; a10 += xb.y * wa.y; a10 += xb.z * wa.z; a10 += xb.w * wa.w;
            a11 += xb.x * wb.x; a11 += xb.y * wb.y; a11 += xb.z * wb.z; a11 += xb.w * wb.w;
        }
        if constexpr (CIN == 256) {
            const float* yr0 = x1 + rg * XP;
            const float* yr1 = x1 + (rg + 32) * XP;
            const float* wr0h = wr0 + 128;
            const float* wr1h = wr1 + 128;
#pragma unroll 8
            for (int ci = 0; ci < 128; ci += 4) {
                float4 xa = *(const float4*)(yr0 + ci);
                float4 xb = *(const float4*)(yr1 + ci);
                float4 wa = *(const float4*)(wr0h + ci);
                float4 wb = *(const float4*)(wr1h + ci);
                a00 += xa.x * wa.x; a00 += xa.y * wa.y; a00 += xa.z * wa.z; a00 += xa.w * wa.w;
                a01 += xa.x * wb.x; a01 += xa.y * wb.y; a01 += xa.z * wb.z; a01 += xa.w * wb.w;
                a10 += xb.x * wa.x; a10 += xb.y * wa.y; a10 += xb.z * wa.z; a10 += xb.w * wa.w;
                a11 += xb.x * wb.x; a11 += xb.y * wb.y; a11 += xb.z * wb.z; a11 += xb.w * wb.w;
            }
        }
        const int c0 = ch * NCH + cg * 2;
        const float b0 = bias[c0], b1 = bias[c0 + 1];
        *(float2*)(outb + rg * XP + c0)        = make_float2(a00 + b0, a01 + b1);
        *(float2*)(outb + (rg + 32) * XP + c0) = make_float2(a10 + b0, a11 + b1);
        __syncthreads();
    }
}

// ---------------------------------------------------------------------------
// Window attention for one direction. 8 warps = 4 heads x 2 row-halves;
// each lane owns one query row (q in regs). 3-pass softmax (max / sum+acc),
// K,V rows read via warp-broadcast LDS. Ob may alias Qb (sync after q-load).
// ---------------------------------------------------------------------------
__device__ __forceinline__ void attention(const float* __restrict__ Qb,
                                          const float* __restrict__ Kb,
                                          const float* __restrict__ Vb,
                                          float* __restrict__ Ob, int tid) {
    const int L = tid & 31, w = tid >> 5;
    const int head = w >> 1;
    const int row  = (w & 1) * 32 + L;
    const float scale = 0.17677669529663687f;  // 32^-0.5

    float4 q[8];
    const float4* qp = (const float4*)(Qb + row * XP + head * 32);
#pragma unroll
    for (int t = 0; t < 8; ++t) {
        q[t] = qp[t];
        q[t].x *= scale; q[t].y *= scale; q[t].z *= scale; q[t].w *= scale;
    }
    __syncthreads();  // all q loaded before Ob (=Qb) is overwritten

    const float* kbase = Kb + head * 32;
    const float* vbase = Vb + head * 32;

    float m = -1e30f;
#pragma unroll 4
    for (int j = 0; j < 64; ++j) {
        const float4* kp = (const float4*)(kbase + j * XP);
        float d0 = 0.f, d1 = 0.f, d2 = 0.f, d3 = 0.f;
#pragma unroll
        for (int t = 0; t < 8; ++t) {
            float4 k4 = kp[t];
            d0 += q[t].x * k4.x; d1 += q[t].y * k4.y;
            d2 += q[t].z * k4.z; d3 += q[t].w * k4.w;
        }
        m = fmaxf(m, (d0 + d1) + (d2 + d3));
    }

    float l = 0.f;
    float4 o[8];
#pragma unroll
    for (int t = 0; t < 8; ++t) o[t] = make_float4(0.f, 0.f, 0.f, 0.f);

#pragma unroll 2
    for (int j = 0; j < 64; ++j) {
        const float4* kp = (const float4*)(kbase + j * XP);
        float d0 = 0.f, d1 = 0.f, d2 = 0.f, d3 = 0.f;
#pragma unroll
        for (int t = 0; t < 8; ++t) {
            float4 k4 = kp[t];
            d0 += q[t].x * k4.x; d1 += q[t].y * k4.y;
            d2 += q[t].z * k4.z; d3 += q[t].w * k4.w;
        }
        float e = __expf(((d0 + d1) + (d2 + d3)) - m);
        l += e;
        const float4* vp = (const float4*)(vbase + j * XP);
#pragma unroll
        for (int t = 0; t < 8; ++t) {
            float4 v4 = vp[t];
            o[t].x += e * v4.x; o[t].y += e * v4.y;
            o[t].z += e * v4.z; o[t].w += e * v4.w;
        }
    }
    const float inv = 1.f / l;
    float4* op = (float4*)(Ob + row * XP + head * 32);
#pragma unroll
    for (int t = 0; t < 8; ++t) {
        o[t].x *= inv; o[t].y *= inv; o[t].z *= inv; o[t].w *= inv;
        op[t] = o[t];
    }
    __syncthreads();
}

__device__ __forceinline__ float sigmoidf_(float x) {
    return 1.f / (1.f + __expf(-x));
}

// ---------------------------------------------------------------------------
extern __shared__ float smem[];

__global__ void __launch_bounds__(TB, 1) cmafm_kernel(P p) {
    float* B0 = smem;            // F_opt window
    float* B1 = smem + BUF;      // F_sar window
    float* B2 = smem + 2 * BUF;  // working
    float* B3 = smem + 3 * BUF;  // working / F_o2s / F_opt_new
    float* B4 = smem + 4 * BUF;  // working / F_s2o / F_sar_new
    float* B5 = smem + 5 * BUF;  // working
    float* wst = smem + 6 * BUF; // weight stage

    const int tid  = threadIdx.x;
    const int widx = blockIdx.x;
    const int b  = widx >> 10;
    const int wh = (widx >> 5) & 31;
    const int ww = widx & 31;
    const int gbase = b * (CC * HH * WWI) + (wh * 8) * WWI + ww * 8;

    load_window(B0, p.F_opt, gbase, tid);
    load_window(B1, p.F_sar, gbase, tid);
    __syncthreads();

    // --- direction opt->sar : Qo, Ks, Vs ---
    gemm<128>(p.wq_opt, p.bq_opt, B0, nullptr, B2, wst);
    gemm<128>(p.wk_sar, p.bk_sar, B1, nullptr, B3, wst);
    gemm<128>(p.wv_sar, p.bv_sar, B1, nullptr, B4, wst);
    attention(B2, B3, B4, B2, tid);
    gemm<128>(p.pw_o2s, p.pb_o2s, B2, nullptr, B3, wst);  // F_o2s -> B3

    // --- direction sar->opt : Qs, Ko, Vo ---
    gemm<128>(p.wq_sar, p.bq_sar, B1, nullptr, B2, wst);
    gemm<128>(p.wk_opt, p.bk_opt, B0, nullptr, B4, wst);
    gemm<128>(p.wv_opt, p.bv_opt, B0, nullptr, B5, wst);
    attention(B2, B4, B5, B2, tid);
    gemm<128>(p.pw_s2o, p.pb_s2o, B2, nullptr, B4, wst);  // F_s2o -> B4

    // --- gate opt: sigma = sigmoid(Wg @ [F_opt ; F_o2s]) ---
    gemm<256>(p.gow, p.gob, B0, B3, B2, wst);
    for (int idx = tid; idx < NPIX * CC; idx += TB) {
        const int off = (idx >> 7) * XP + (idx & 127);
        const float s = sigmoidf_(B2[off]);
        B2[off] = s;
        B3[off] = B0[off] + s * B3[off];   // F_opt_new
    }
    __syncthreads();
    store_window(p.out + NTOT, B2, gbase, tid);  // sigma_opt

    // --- gate sar ---
    gemm<256>(p.gsw, p.gsb, B1, B4, B2, wst);    // internal sync orders prior store
    for (int idx = tid; idx < NPIX * CC; idx += TB) {
        const int off = (idx >> 7) * XP + (idx & 127);
        const float s = sigmoidf_(B2[off]);
        B2[off] = s;
        B4[off] = B1[off] + s * B4[off];   // F_sar_new
    }
    __syncthreads();
    store_window(p.out + 2 * NTOT, B2, gbase, tid);  // sigma_sar

    // --- fuse + BN + SiLU ---
    gemm<256>(p.fw, p.fb, B3, B4, B2, wst);
    {
        const int c = tid >> 1, qq = tid & 1;
        const float inv = p.gma[c] * rsqrtf(p.var[c] + 1e-5f);
        const float sh  = p.bta[c] - p.mu[c] * inv;
        float* g = p.out + gbase + c * (HH * WWI) + qq * 4;
        const float* sp0 = B2 + qq * 4 * XP + c;
#pragma unroll
        for (int i = 0; i < 8; ++i) {
            const float* sp = sp0 + i * 8 * XP;
            float y0 = sp[0]      * inv + sh;
            float y1 = sp[XP]     * inv + sh;
            float y2 = sp[2 * XP] * inv + sh;
            float y3 = sp[3 * XP] * inv + sh;
            y0 *= sigmoidf_(y0); y1 *= sigmoidf_(y1);
            y2 *= sigmoidf_(y2); y3 *= sigmoidf_(y3);
            *(float4*)(g + i * WWI) = make_float4(y0, y1, y2, y3);
        }
    }
}

// ---------------------------------------------------------------------------
extern "C" void kernel_launch(void* const* d_in, const int* in_sizes, int n_in,
                              void* d_out, int out_size) {
    (void)in_sizes; (void)n_in; (void)out_size;
    P p;
    p.F_opt  = (const float*)d_in[0];  p.F_sar  = (const float*)d_in[1];
    p.wq_opt = (const float*)d_in[2];  p.bq_opt = (const float*)d_in[3];
    p.wk_opt = (const float*)d_in[4];  p.bk_opt = (const float*)d_in[5];
    p.wv_opt = (const float*)d_in[6];  p.bv_opt = (const float*)d_in[7];
    p.wq_sar = (const float*)d_in[8];  p.bq_sar = (const float*)d_in[9];
    p.wk_sar = (const float*)d_in[10]; p.bk_sar = (const float*)d_in[11];
    p.wv_sar = (const float*)d_in[12]; p.bv_sar = (const float*)d_in[13];
    p.pw_o2s = (const float*)d_in[14]; p.pb_o2s = (const float*)d_in[15];
    p.pw_s2o = (const float*)d_in[16]; p.pb_s2o = (const float*)d_in[17];
    p.gow    = (const float*)d_in[18]; p.gob    = (const float*)d_in[19];
    p.gsw    = (const float*)d_in[20]; p.gsb    = (const float*)d_in[21];
    p.fw     = (const float*)d_in[22]; p.fb     = (const float*)d_in[23];
    p.gma    = (const float*)d_in[24]; p.bta    = (const float*)d_in[25];
    p.mu     = (const float*)d_in[26]; p.var    = (const float*)d_in[27];
    p.out    = (float*)d_out;

    const size_t smem_bytes = SMEM_FLOATS * sizeof(float);  // 219392
    cudaFuncSetAttribute(cmafm_kernel, cudaFuncAttributeMaxDynamicSharedMemorySize,
                         (int)smem_bytes);
    cmafm_kernel<<<4096, TB, smem_bytes>>>(p);
}

// round 2
// speedup vs baseline: 1.7170x; 1.7170x over previous
#include <cuda_runtime.h>
#include <cstdint>

// ---------------------------------------------------------------------------
// CMAFM block, fully fused: one CTA per 8x8 window. All intermediates in smem.
// B=4, C=128, H=W=256, WS=8 -> 4096 windows. 256 threads/CTA.
// GEMMs: 4x4 per-thread micro-tile (rows/cols strided by 16), 64-out-col
// chunks with weights staged into a rotating dead smem buffer.
// ---------------------------------------------------------------------------

#define TB 256

constexpr int CC    = 128;
constexpr int HH    = 256;
constexpr int WWI   = 256;
constexpr int NPIX  = 64;
constexpr int XP    = 132;        // smem row pitch (floats)
constexpr int WPI   = 132;        // weight stage pitch
constexpr int BUF   = NPIX * XP;  // 8448 floats
constexpr int SMEM_FLOATS = 6 * BUF;          // 50688 floats = 202752 B
constexpr size_t NTOT = 4ull * 128 * 256 * 256;

struct P {
    const float *F_opt, *F_sar;
    const float *wq_opt, *bq_opt, *wk_opt, *bk_opt, *wv_opt, *bv_opt;
    const float *wq_sar, *bq_sar, *wk_sar, *bk_sar, *wv_sar, *bv_sar;
    const float *pw_o2s, *pb_o2s, *pw_s2o, *pb_s2o;
    const float *gow, *gob, *gsw, *gsb;
    const float *fw, *fb;
    const float *gma, *bta, *mu, *var;
    float *out;
};

// Load one window (64 px x 128 ch) from NCHW global into smem [n][c].
__device__ __forceinline__ void load_window(float* dst, const float* __restrict__ src,
                                            int gbase, int tid) {
    const int c = tid >> 1, qq = tid & 1;
    const float* s = src + gbase + c * (HH * WWI) + qq * 4;
#pragma unroll
    for (int i = 0; i < 8; ++i) {
        float4 v = *(const float4*)(s + i * WWI);
        float* d = dst + (i * 8 + qq * 4) * XP + c;
        d[0] = v.x; d[XP] = v.y; d[2 * XP] = v.z; d[3 * XP] = v.w;
    }
}

// Transposed store: smem [n][c] -> NCHW global.
__device__ __forceinline__ void store_window(float* __restrict__ g, const float* sbuf,
                                             int gbase, int tid) {
    const int c = tid >> 1, qq = tid & 1;
    float* gp = g + gbase + c * (HH * WWI) + qq * 4;
    const float* sp0 = sbuf + qq * 4 * XP + c;
#pragma unroll
    for (int i = 0; i < 8; ++i) {
        const float* sp = sp0 + i * 8 * XP;
        *(float4*)(gp + i * WWI) = make_float4(sp[0], sp[XP], sp[2 * XP], sp[3 * XP]);
    }
}

// Accumulate acc[4][4] += X(rows rg+16i) dot W(staged rows cg+16j) over k=128.
__device__ __forceinline__ void accum_k128(float acc[4][4],
                                           const float* __restrict__ x, int rg,
                                           const float* __restrict__ wst, int cg) {
    const float* xr0 = x + rg * XP;
    const float* xr1 = xr0 + 16 * XP;
    const float* xr2 = xr1 + 16 * XP;
    const float* xr3 = xr2 + 16 * XP;
    const float* wr0 = wst + cg * WPI;
    const float* wr1 = wr0 + 16 * WPI;
    const float* wr2 = wr1 + 16 * WPI;
    const float* wr3 = wr2 + 16 * WPI;
#pragma unroll 2
    for (int ci = 0; ci < 128; ci += 4) {
        float4 xa0 = *(const float4*)(xr0 + ci);
        float4 xa1 = *(const float4*)(xr1 + ci);
        float4 xa2 = *(const float4*)(xr2 + ci);
        float4 xa3 = *(const float4*)(xr3 + ci);
        float4 wb0 = *(const float4*)(wr0 + ci);
        float4 wb1 = *(const float4*)(wr1 + ci);
        float4 wb2 = *(const float4*)(wr2 + ci);
        float4 wb3 = *(const float4*)(wr3 + ci);
#define DOT(i, j, xa, wb) \
        acc[i][j] += xa.x * wb.x; acc[i][j] += xa.y * wb.y; \
        acc[i][j] += xa.z * wb.z; acc[i][j] += xa.w * wb.w;
        DOT(0,0,xa0,wb0) DOT(0,1,xa0,wb1) DOT(0,2,xa0,wb2) DOT(0,3,xa0,wb3)
        DOT(1,0,xa1,wb0) DOT(1,1,xa1,wb1) DOT(1,2,xa1,wb2) DOT(1,3,xa1,wb3)
        DOT(2,0,xa2,wb0) DOT(2,1,xa2,wb1) DOT(2,2,xa2,wb2) DOT(2,3,xa2,wb3)
        DOT(3,0,xa3,wb0) DOT(3,1,xa3,wb1) DOT(3,2,xa3,wb2) DOT(3,3,xa3,wb3)
#undef DOT
    }
}

// out[64][128] = X[64][128] @ W^T + bias. Two chunks of 64 out-cols; each
// chunk's 64x128 weights staged into wst (one full BUF). Syncs internally.
__device__ __noinline__ void gemm128(const float* __restrict__ Wg,
                                     const float* __restrict__ bias,
                                     const float* __restrict__ x,
                                     float* __restrict__ outb,
                                     float* __restrict__ wst) {
    const int tid = threadIdx.x;
    const int L = tid & 31, w = tid >> 5;
    const int rg = (L & 3) | ((w & 3) << 2);     // 0..15
    const int cg = (L >> 2) | ((w >> 2) << 3);   // 0..15

    for (int ch = 0; ch < 2; ++ch) {
        const int c0 = ch * 64;
        __syncthreads();  // protect wst from previous readers
#pragma unroll
        for (int it = 0; it < 8; ++it) {
            const int idx = tid * 4 + it * TB * 4;
            const int r = idx >> 7, k = idx & 127;
            float4 v = *(const float4*)(Wg + (c0 + r) * 128 + k);
            *(float4*)(wst + r * WPI + k) = v;
        }
        __syncthreads();

        float acc[4][4];
#pragma unroll
        for (int i = 0; i < 4; ++i)
#pragma unroll
            for (int j = 0; j < 4; ++j) acc[i][j] = 0.f;

        accum_k128(acc, x, rg, wst, cg);

#pragma unroll
        for (int j = 0; j < 4; ++j) {
            const int cc = c0 + cg + 16 * j;
            const float b = __ldg(bias + cc);
#pragma unroll
            for (int i = 0; i < 4; ++i)
                outb[(rg + 16 * i) * XP + cc] = acc[i][j] + b;
        }
    }
    __syncthreads();
}

// out[64][128] = [X0|X1][64][256] @ W^T + bias, W row-major [128][256].
__device__ __noinline__ void gemm256(const float* __restrict__ Wg,
                                     const float* __restrict__ bias,
                                     const float* __restrict__ x0,
                                     const float* __restrict__ x1,
                                     float* __restrict__ outb,
                                     float* __restrict__ wst) {
    const int tid = threadIdx.x;
    const int L = tid & 31, w = tid >> 5;
    const int rg = (L & 3) | ((w & 3) << 2);
    const int cg = (L >> 2) | ((w >> 2) << 3);

    for (int ch = 0; ch < 2; ++ch) {
        const int c0 = ch * 64;
        float acc[4][4];
#pragma unroll
        for (int i = 0; i < 4; ++i)
#pragma unroll
            for (int j = 0; j < 4; ++j) acc[i][j] = 0.f;

        for (int h = 0; h < 2; ++h) {
            __syncthreads();
#pragma unroll
            for (int it = 0; it < 8; ++it) {
                const int idx = tid * 4 + it * TB * 4;
                const int r = idx >> 7, k = idx & 127;
                float4 v = *(const float4*)(Wg + (c0 + r) * 256 + h * 128 + k);
                *(float4*)(wst + r * WPI + k) = v;
            }
            __syncthreads();
            accum_k128(acc, h ? x1 : x0, rg, wst, cg);
        }

#pragma unroll
        for (int j = 0; j < 4; ++j) {
            const int cc = c0 + cg + 16 * j;
            const float b = __ldg(bias + cc);
#pragma unroll
            for (int i = 0; i < 4; ++i)
                outb[(rg + 16 * i) * XP + cc] = acc[i][j] + b;
        }
    }
    __syncthreads();
}

// Window attention: 8 warps = 4 heads x 2 row-halves; lane owns one query row.
// Ob may alias Qb (sync after q-load).
__device__ __forceinline__ void attention(const float* __restrict__ Qb,
                                          const float* __restrict__ Kb,
                                          const float* __restrict__ Vb,
                                          float* __restrict__ Ob, int tid) {
    const int L = tid & 31, w = tid >> 5;
    const int head = w >> 1;
    const int row  = (w & 1) * 32 + L;
    const float scale = 0.17677669529663687f;  // 32^-0.5

    float4 q[8];
    const float4* qp = (const float4*)(Qb + row * XP + head * 32);
#pragma unroll
    for (int t = 0; t < 8; ++t) {
        q[t] = qp[t];
        q[t].x *= scale; q[t].y *= scale; q[t].z *= scale; q[t].w *= scale;
    }
    __syncthreads();

    const float* kbase = Kb + head * 32;
    const float* vbase = Vb + head * 32;

    float m = -1e30f;
#pragma unroll 4
    for (int j = 0; j < 64; ++j) {
        const float4* kp = (const float4*)(kbase + j * XP);
        float d0 = 0.f, d1 = 0.f, d2 = 0.f, d3 = 0.f;
#pragma unroll
        for (int t = 0; t < 8; ++t) {
            float4 k4 = kp[t];
            d0 += q[t].x * k4.x; d1 += q[t].y * k4.y;
            d2 += q[t].z * k4.z; d3 += q[t].w * k4.w;
        }
        m = fmaxf(m, (d0 + d1) + (d2 + d3));
    }

    float l = 0.f;
    float4 o[8];
#pragma unroll
    for (int t = 0; t < 8; ++t) o[t] = make_float4(0.f, 0.f, 0.f, 0.f);

#pragma unroll 2
    for (int j = 0; j < 64; ++j) {
        const float4* kp = (const float4*)(kbase + j * XP);
        float d0 = 0.f, d1 = 0.f, d2 = 0.f, d3 = 0.f;
#pragma unroll
        for (int t = 0; t < 8; ++t) {
            float4 k4 = kp[t];
            d0 += q[t].x * k4.x; d1 += q[t].y * k4.y;
            d2 += q[t].z * k4.z; d3 += q[t].w * k4.w;
        }
        float e = __expf(((d0 + d1) + (d2 + d3)) - m);
        l += e;
        const float4* vp = (const float4*)(vbase + j * XP);
#pragma unroll
        for (int t = 0; t < 8; ++t) {
            float4 v4 = vp[t];
            o[t].x += e * v4.x; o[t].y += e * v4.y;
            o[t].z += e * v4.z; o[t].w += e * v4.w;
        }
    }
    const float inv = 1.f / l;
    float4* op = (float4*)(Ob + row * XP + head * 32);
#pragma unroll
    for (int t = 0; t < 8; ++t) {
        o[t].x *= inv; o[t].y *= inv; o[t].z *= inv; o[t].w *= inv;
        op[t] = o[t];
    }
    __syncthreads();
}

__device__ __forceinline__ float sigmoidf_(float x) {
    return 1.f / (1.f + __expf(-x));
}

extern __shared__ float smem[];

__global__ void __launch_bounds__(TB, 1) cmafm_kernel(P p) {
    float* B0 = smem;
    float* B1 = smem + BUF;
    float* B2 = smem + 2 * BUF;
    float* B3 = smem + 3 * BUF;
    float* B4 = smem + 4 * BUF;
    float* B5 = smem + 5 * BUF;

    const int tid  = threadIdx.x;
    const int widx = blockIdx.x;
    const int b  = widx >> 10;
    const int wh = (widx >> 5) & 31;
    const int ww = widx & 31;
    const int gbase = b * (CC * HH * WWI) + (wh * 8) * WWI + ww * 8;

    load_window(B0, p.F_opt, gbase, tid);
    load_window(B1, p.F_sar, gbase, tid);
    __syncthreads();

    // --- direction opt->sar : Qo, Ks, Vs ---
    gemm128(p.wq_opt, p.bq_opt, B0, B2, B3);
    gemm128(p.wk_sar, p.bk_sar, B1, B3, B4);
    gemm128(p.wv_sar, p.bv_sar, B1, B4, B5);
    attention(B2, B3, B4, B2, tid);
    gemm128(p.pw_o2s, p.pb_o2s, B2, B3, B4);   // F_o2s -> B3

    // --- direction sar->opt : Vo, Ko, Qs ---
    gemm128(p.wv_opt, p.bv_opt, B0, B4, B5);
    gemm128(p.wk_opt, p.bk_opt, B0, B5, B2);
    gemm128(p.wq_sar, p.bq_sar, B1, B2, B0);   // B0 sacrificed as wst
    attention(B2, B5, B4, B2, tid);
    gemm128(p.pw_s2o, p.pb_s2o, B2, B4, B5);   // F_s2o -> B4

    // reload F_opt (B0 was clobbered as weight stage)
    load_window(B0, p.F_opt, gbase, tid);

    // --- gate opt ---  (gemm's leading sync orders the reload of B0)
    gemm256(p.gow, p.gob, B0, B3, B5, B2);
    for (int idx = tid; idx < NPIX * CC; idx += TB) {
        const int off = (idx >> 7) * XP + (idx & 127);
        const float s = sigmoidf_(B5[off]);
        B5[off] = s;
        B3[off] = B0[off] + s * B3[off];       // F_opt_new
    }
    __syncthreads();
    store_window(p.out + NTOT, B5, gbase, tid);    // sigma_opt

    // --- gate sar ---  (gemm's leading sync orders the B5 store reads)
    gemm256(p.gsw, p.gsb, B1, B4, B2, B5);
    for (int idx = tid; idx < NPIX * CC; idx += TB) {
        const int off = (idx >> 7) * XP + (idx & 127);
        const float s = sigmoidf_(B2[off]);
        B2[off] = s;
        B4[off] = B1[off] + s * B4[off];       // F_sar_new
    }
    __syncthreads();
    store_window(p.out + 2 * NTOT, B2, gbase, tid);  // sigma_sar

    // --- fuse + BN + SiLU ---
    gemm256(p.fw, p.fb, B3, B4, B5, B2);
    {
        const int c = tid >> 1, qq = tid & 1;
        const float inv = p.gma[c] * rsqrtf(p.var[c] + 1e-5f);
        const float sh  = p.bta[c] - p.mu[c] * inv;
        float* g = p.out + gbase + c * (HH * WWI) + qq * 4;
        const float* sp0 = B5 + qq * 4 * XP + c;
#pragma unroll
        for (int i = 0; i < 8; ++i) {
            const float* sp = sp0 + i * 8 * XP;
            float y0 = sp[0]      * inv + sh;
            float y1 = sp[XP]     * inv + sh;
            float y2 = sp[2 * XP] * inv + sh;
            float y3 = sp[3 * XP] * inv + sh;
            y0 *= sigmoidf_(y0); y1 *= sigmoidf_(y1);
            y2 *= sigmoidf_(y2); y3 *= sigmoidf_(y3);
            *(float4*)(g + i * WWI) = make_float4(y0, y1, y2, y3);
        }
    }
}

extern "C" void kernel_launch(void* const* d_in, const int* in_sizes, int n_in,
                              void* d_out, int out_size) {
    (void)in_sizes; (void)n_in; (void)out_size;
    P p;
    p.F_opt  = (const float*)d_in[0];  p.F_sar  = (const float*)d_in[1];
    p.wq_opt = (const float*)d_in[2];  p.bq_opt = (const float*)d_in[3];
    p.wk_opt = (const float*)d_in[4];  p.bk_opt = (const float*)d_in[5];
    p.wv_opt = (const float*)d_in[6];  p.bv_opt = (const float*)d_in[7];
    p.wq_sar = (const float*)d_in[8];  p.bq_sar = (const float*)d_in[9];
    p.wk_sar = (const float*)d_in[10]; p.bk_sar = (const float*)d_in[11];
    p.wv_sar = (const float*)d_in[12]; p.bv_sar = (const float*)d_in[13];
    p.pw_o2s = (const float*)d_in[14]; p.pb_o2s = (const float*)d_in[15];
    p.pw_s2o = (const float*)d_in[16]; p.pb_s2o = (const float*)d_in[17];
    p.gow    = (const float*)d_in[18]; p.gob    = (const float*)d_in[19];
    p.gsw    = (const float*)d_in[20]; p.gsb    = (const float*)d_in[21];
    p.fw     = (const float*)d_in[22]; p.fb     = (const float*)d_in[23];
    p.gma    = (const float*)d_in[24]; p.bta    = (const float*)d_in[25];
    p.mu     = (const float*)d_in[26]; p.var    = (const float*)d_in[27];
    p.out    = (float*)d_out;

    const size_t smem_bytes = SMEM_FLOATS * sizeof(float);  // 202752
    cudaFuncSetAttribute(cmafm_kernel, cudaFuncAttributeMaxDynamicSharedMemorySize,
                         (int)smem_bytes);
    cmafm_kernel<<<4096, TB, smem_bytes>>>(p);
}

// round 4
// speedup vs baseline: 1.9784x; 1.1522x over previous
#include <cuda_runtime.h>
#include <cstdint>

// ---------------------------------------------------------------------------
// CMAFM block, fully fused: one CTA per 8x8 window. 4096 CTAs, 256 thr.
// GEMMs: 4x8 micro-tile over full 64x128 output, k staged in 64-wide halves,
// f32x2 packed FMA accumulation. 5 rotating data buffers + dedicated W stage.
// ---------------------------------------------------------------------------

#define TB 256
using u64 = unsigned long long;

constexpr int CC    = 128;
constexpr int HH    = 256;
constexpr int WWI   = 256;
constexpr int NPIX  = 64;
constexpr int XP    = 132;          // data buffer row pitch (floats)
constexpr int WPI   = 68;           // weight stage pitch (floats)
constexpr int BUF   = NPIX * XP;    // 8448 floats
constexpr int WSTF  = 128 * WPI;    // 8704 floats
constexpr int SMEM_FLOATS = 5 * BUF + WSTF;   // 50944 floats = 203776 B
constexpr size_t NTOT = 4ull * 128 * 256 * 256;

struct P {
    const float *F_opt, *F_sar;
    const float *wq_opt, *bq_opt, *wk_opt, *bk_opt, *wv_opt, *bv_opt;
    const float *wq_sar, *bq_sar, *wk_sar, *bk_sar, *wv_sar, *bv_sar;
    const float *pw_o2s, *pb_o2s, *pw_s2o, *pb_s2o;
    const float *gow, *gob, *gsw, *gsb;
    const float *fw, *fb;
    const float *gma, *bta, *mu, *var;
    float *out;
};

// ---- f32x2 helpers (FFMA2 path; ptxas never emits these from C++) ---------
__device__ __forceinline__ void f2fma(u64& d, u64 a, u64 b) {
    asm("fma.rn.f32x2 %0, %1, %2, %0;" : "+l"(d) : "l"(a), "l"(b));
}
__device__ __forceinline__ u64 f2mul(u64 a, u64 b) {
    u64 d; asm("mul.rn.f32x2 %0, %1, %2;" : "=l"(d) : "l"(a), "l"(b)); return d;
}
__device__ __forceinline__ u64 f2add(u64 a, u64 b) {
    u64 d; asm("add.rn.f32x2 %0, %1, %2;" : "=l"(d) : "l"(a), "l"(b)); return d;
}
__device__ __forceinline__ u64 dup2(float v) {
    u64 d; asm("mov.b64 %0, {%1, %1};" : "=l"(d) : "f"(v)); return d;
}
__device__ __forceinline__ float f2sum(u64 a) {
    float lo, hi; asm("mov.b64 {%0, %1}, %2;" : "=f"(lo), "=f"(hi) : "l"(a));
    return lo + hi;
}

// Load one window (64 px x 128 ch) from NCHW global into smem [n][c].
__device__ __forceinline__ void load_window(float* dst, const float* __restrict__ src,
                                            int gbase, int tid) {
    const int c = tid >> 1, qq = tid & 1;
    const float* s = src + gbase + c * (HH * WWI) + qq * 4;
#pragma unroll
    for (int i = 0; i < 8; ++i) {
        float4 v = *(const float4*)(s + i * WWI);
        float* d = dst + (i * 8 + qq * 4) * XP + c;
        d[0] = v.x; d[XP] = v.y; d[2 * XP] = v.z; d[3 * XP] = v.w;
    }
}

// Transposed store: smem [n][c] -> NCHW global.
__device__ __forceinline__ void store_window(float* __restrict__ g, const float* sbuf,
                                             int gbase, int tid) {
    const int c = tid >> 1, qq = tid & 1;
    float* gp = g + gbase + c * (HH * WWI) + qq * 4;
    const float* sp0 = sbuf + qq * 4 * XP + c;
#pragma unroll
    for (int i = 0; i < 8; ++i) {
        const float* sp = sp0 + i * 8 * XP;
        *(float4*)(gp + i * WWI) = make_float4(sp[0], sp[XP], sp[2 * XP], sp[3 * XP]);
    }
}

// ---------------------------------------------------------------------------
// out[64][128] = [x0 | x1][64][CIN] @ W^T + bias.  W row-major [128][CIN].
// 4x8 per-thread tile (rows rg+16i, cols cg+16j). k in 64-wide staged halves
// with register prefetch of the next half. In-place (outb==x0) is safe.
// ---------------------------------------------------------------------------
__device__ __noinline__ void gemm_core(const float* __restrict__ Wg, int CIN,
                                       const float* __restrict__ bias,
                                       const float* __restrict__ x0,
                                       const float* __restrict__ x1,
                                       float* __restrict__ outb,
                                       float* __restrict__ wst) {
    const int tid = threadIdx.x;
    const int L = tid & 31, w = tid >> 5;
    const int rg = (L & 3) | ((w & 3) << 2);     // 0..15
    const int cg = (L >> 2) | ((w >> 2) << 3);   // 0..15
    const int nh = CIN >> 6;
    const int sc = tid >> 4;                     // stage row base (0..15)
    const int sk = (tid * 4) & 63;               // stage k offset

    u64 acc[4][8];
#pragma unroll
    for (int i = 0; i < 4; ++i)
#pragma unroll
        for (int j = 0; j < 8; ++j) acc[i][j] = 0ull;

    float4 stg[8];
#pragma unroll
    for (int it = 0; it < 8; ++it)
        stg[it] = *(const float4*)(Wg + (sc + it * 16) * CIN + sk);

    for (int h = 0; h < nh; ++h) {
        __syncthreads();  // wst free, prior outputs/readers settled
#pragma unroll
        for (int it = 0; it < 8; ++it)
            *(float4*)(wst + (sc + it * 16) * WPI + sk) = stg[it];
        if (h + 1 < nh) {
            const float* Wn = Wg + (h + 1) * 64;
#pragma unroll
            for (int it = 0; it < 8; ++it)
                stg[it] = *(const float4*)(Wn + (sc + it * 16) * CIN + sk);
        }
        __syncthreads();

        const float* xs = ((h >= 2) ? x1 : x0) + (h & 1) * 64 + rg * XP;
        const float* wr = wst + cg * WPI;
#pragma unroll 2
        for (int ci = 0; ci < 64; ci += 4) {
            ulonglong2 xa0 = *(const ulonglong2*)(xs + ci);
            ulonglong2 xa1 = *(const ulonglong2*)(xs + 16 * XP + ci);
            ulonglong2 xa2 = *(const ulonglong2*)(xs + 32 * XP + ci);
            ulonglong2 xa3 = *(const ulonglong2*)(xs + 48 * XP + ci);
            ulonglong2 wb0 = *(const ulonglong2*)(wr + ci);
            ulonglong2 wb1 = *(const ulonglong2*)(wr + 16 * WPI + ci);
            ulonglong2 wb2 = *(const ulonglong2*)(wr + 32 * WPI + ci);
            ulonglong2 wb3 = *(const ulonglong2*)(wr + 48 * WPI + ci);
            ulonglong2 wb4 = *(const ulonglong2*)(wr + 64 * WPI + ci);
            ulonglong2 wb5 = *(const ulonglong2*)(wr + 80 * WPI + ci);
            ulonglong2 wb6 = *(const ulonglong2*)(wr + 96 * WPI + ci);
            ulonglong2 wb7 = *(const ulonglong2*)(wr + 112 * WPI + ci);
#define ROW(i, xa) \
            f2fma(acc[i][0], xa.x, wb0.x); f2fma(acc[i][0], xa.y, wb0.y); \
            f2fma(acc[i][1], xa.x, wb1.x); f2fma(acc[i][1], xa.y, wb1.y); \
            f2fma(acc[i][2], xa.x, wb2.x); f2fma(acc[i][2], xa.y, wb2.y); \
            f2fma(acc[i][3], xa.x, wb3.x); f2fma(acc[i][3], xa.y, wb3.y); \
            f2fma(acc[i][4], xa.x, wb4.x); f2fma(acc[i][4], xa.y, wb4.y); \
            f2fma(acc[i][5], xa.x, wb5.x); f2fma(acc[i][5], xa.y, wb5.y); \
            f2fma(acc[i][6], xa.x, wb6.x); f2fma(acc[i][6], xa.y, wb6.y); \
            f2fma(acc[i][7], xa.x, wb7.x); f2fma(acc[i][7], xa.y, wb7.y);
            ROW(0, xa0) ROW(1, xa1) ROW(2, xa2) ROW(3, xa3)
#undef ROW
        }
    }
    __syncthreads();  // all reads of x done before (possibly in-place) writes
#pragma unroll
    for (int j = 0; j < 8; ++j) {
        const int cc = cg + 16 * j;
        const float b = __ldg(bias + cc);
#pragma unroll
        for (int i = 0; i < 4; ++i)
            outb[(rg + 16 * i) * XP + cc] = f2sum(acc[i][j]) + b;
    }
    __syncthreads();
}

// ---------------------------------------------------------------------------
// Window attention: 8 warps = 4 heads x 2 row-halves; lane owns one query row.
// Full head_dim = 32 floats = 16 packed f32x2 lanes. Ob may alias Qb.
// ---------------------------------------------------------------------------
__device__ __forceinline__ void attention(const float* __restrict__ Qb,
                                          const float* __restrict__ Kb,
                                          const float* __restrict__ Vb,
                                          float* __restrict__ Ob, int tid) {
    const int L = tid & 31, w = tid >> 5;
    const int head = w >> 1;
    const int row  = (w & 1) * 32 + L;

    u64 q[16];
    {
        const ulonglong2* qp = (const ulonglong2*)(Qb + row * XP + head * 32);
        const u64 sc2 = dup2(0.17677669529663687f);  // 32^-0.5
#pragma unroll
        for (int t = 0; t < 8; ++t) {
            ulonglong2 v = qp[t];
            q[2 * t]     = f2mul(v.x, sc2);
            q[2 * t + 1] = f2mul(v.y, sc2);
        }
    }
    __syncthreads();  // all q loaded before Ob (=Qb) is overwritten

    const float* kbase = Kb + head * 32;
    const float* vbase = Vb + head * 32;

    float m = -1e30f;
#pragma unroll 2
    for (int j = 0; j < 64; ++j) {
        const ulonglong2* kp = (const ulonglong2*)(kbase + j * XP);
        u64 d0 = 0ull, d1 = 0ull, d2 = 0ull, d3 = 0ull;
#pragma unroll
        for (int t = 0; t < 4; ++t) {
            ulonglong2 ka = kp[2 * t], kb = kp[2 * t + 1];
            f2fma(d0, q[4 * t],     ka.x);
            f2fma(d1, q[4 * t + 1], ka.y);
            f2fma(d2, q[4 * t + 2], kb.x);
            f2fma(d3, q[4 * t + 3], kb.y);
        }
        m = fmaxf(m, f2sum(f2add(f2add(d0, d1), f2add(d2, d3))));
    }

    float l = 0.f;
    u64 o[16];
#pragma unroll
    for (int t = 0; t < 16; ++t) o[t] = 0ull;

    for (int j = 0; j < 64; ++j) {
        const ulonglong2* kp = (const ulonglong2*)(kbase + j * XP);
        u64 d0 = 0ull, d1 = 0ull, d2 = 0ull, d3 = 0ull;
#pragma unroll
        for (int t = 0; t < 4; ++t) {
            ulonglong2 ka = kp[2 * t], kb = kp[2 * t + 1];
            f2fma(d0, q[4 * t],     ka.x);
            f2fma(d1, q[4 * t + 1], ka.y);
            f2fma(d2, q[4 * t + 2], kb.x);
            f2fma(d3, q[4 * t + 3], kb.y);
        }
        const float e = __expf(f2sum(f2add(f2add(d0, d1), f2add(d2, d3))) - m);
        l += e;
        const u64 ee = dup2(e);
        const ulonglong2* vp = (const ulonglong2*)(vbase + j * XP);
#pragma unroll
        for (int t = 0; t < 8; ++t) {
            ulonglong2 v2 = vp[t];
            f2fma(o[2 * t],     ee, v2.x);
            f2fma(o[2 * t + 1], ee, v2.y);
        }
    }
    const u64 inv2 = dup2(1.f / l);
    ulonglong2* op = (ulonglong2*)(Ob + row * XP + head * 32);
#pragma unroll
    for (int t = 0; t < 8; ++t) {
        ulonglong2 r;
        r.x = f2mul(o[2 * t], inv2);
        r.y = f2mul(o[2 * t + 1], inv2);
        op[t] = r;
    }
    __syncthreads();
}

__device__ __forceinline__ float sigmoidf_(float x) {
    return 1.f / (1.f + __expf(-x));
}

extern __shared__ float smem[];

__global__ void __launch_bounds__(TB, 1) cmafm_kernel(P p) {
    float* B0 = smem;
    float* B1 = smem + BUF;
    float* B2 = smem + 2 * BUF;
    float* B3 = smem + 3 * BUF;
    float* B4 = smem + 4 * BUF;
    float* WST = smem + 5 * BUF;

    const int tid  = threadIdx.x;
    const int widx = blockIdx.x;
    const int b  = widx >> 10;
    const int wh = (widx >> 5) & 31;
    const int ww = widx & 31;
    const int gbase = b * (CC * HH * WWI) + (wh * 8) * WWI + ww * 8;

    load_window(B0, p.F_opt, gbase, tid);
    load_window(B1, p.F_sar, gbase, tid);

    // --- direction opt->sar ---
    gemm_core(p.wq_opt, 128, p.bq_opt, B0, nullptr, B2, WST);   // Qo
    gemm_core(p.wk_sar, 128, p.bk_sar, B1, nullptr, B3, WST);   // Ks
    gemm_core(p.wv_sar, 128, p.bv_sar, B1, nullptr, B4, WST);   // Vs
    attention(B2, B3, B4, B2, tid);
    gemm_core(p.pw_o2s, 128, p.pb_o2s, B2, nullptr, B3, WST);   // F_o2s -> B3

    // --- direction sar->opt ---
    gemm_core(p.wq_sar, 128, p.bq_sar, B1, nullptr, B2, WST);   // Qs
    gemm_core(p.wk_opt, 128, p.bk_opt, B0, nullptr, B4, WST);   // Ko
    gemm_core(p.wv_opt, 128, p.bv_opt, B0, nullptr, B0, WST);   // Vo (in-place)
    attention(B2, B4, B0, B2, tid);
    load_window(B0, p.F_opt, gbase, tid);                       // reload F_opt
    gemm_core(p.pw_s2o, 128, p.pb_s2o, B2, nullptr, B4, WST);   // F_s2o -> B4

    // --- gate opt: sigma = sigmoid(Wg @ [F_opt ; F_o2s]) ---
    gemm_core(p.gow, 256, p.gob, B0, B3, B2, WST);
    for (int idx = tid; idx < NPIX * CC; idx += TB) {
        const int off = (idx >> 7) * XP + (idx & 127);
        const float s = sigmoidf_(B2[off]);
        B2[off] = s;
        B3[off] = B0[off] + s * B3[off];       // F_opt_new
    }
    __syncthreads();
    store_window(p.out + NTOT, B2, gbase, tid);      // sigma_opt

    // --- gate sar ---
    gemm_core(p.gsw, 256, p.gsb, B1, B4, B0, WST);   // leading sync orders above
    for (int idx = tid; idx < NPIX * CC; idx += TB) {
        const int off = (idx >> 7) * XP + (idx & 127);
        const float s = sigmoidf_(B0[off]);
        B0[off] = s;
        B4[off] = B1[off] + s * B4[off];       // F_sar_new
    }
    __syncthreads();
    store_window(p.out + 2 * NTOT, B0, gbase, tid);  // sigma_sar

    // --- fuse + BN + SiLU ---
    gemm_core(p.fw, 256, p.fb, B3, B4, B2, WST);
    {
        const int c = tid >> 1, qq = tid & 1;
        const float inv = p.gma[c] * rsqrtf(p.var[c] + 1e-5f);
        const float sh  = p.bta[c] - p.mu[c] * inv;
        float* g = p.out + gbase + c * (HH * WWI) + qq * 4;
        const float* sp0 = B2 + qq * 4 * XP + c;
#pragma unroll
        for (int i = 0; i < 8; ++i) {
            const float* sp = sp0 + i * 8 * XP;
            float y0 = sp[0]      * inv + sh;
            float y1 = sp[XP]     * inv + sh;
            float y2 = sp[2 * XP] * inv + sh;
            float y3 = sp[3 * XP] * inv + sh;
            y0 *= sigmoidf_(y0); y1 *= sigmoidf_(y1);
            y2 *= sigmoidf_(y2); y3 *= sigmoidf_(y3);
            *(float4*)(g + i * WWI) = make_float4(y0, y1, y2, y3);
        }
    }
}

extern "C" void kernel_launch(void* const* d_in, const int* in_sizes, int n_in,
                              void* d_out, int out_size) {
    (void)in_sizes; (void)n_in; (void)out_size;
    P p;
    p.F_opt  = (const float*)d_in[0];  p.F_sar  = (const float*)d_in[1];
    p.wq_opt = (const float*)d_in[2];  p.bq_opt = (const float*)d_in[3];
    p.wk_opt = (const float*)d_in[4];  p.bk_opt = (const float*)d_in[5];
    p.wv_opt = (const float*)d_in[6];  p.bv_opt = (const float*)d_in[7];
    p.wq_sar = (const float*)d_in[8];  p.bq_sar = (const float*)d_in[9];
    p.wk_sar = (const float*)d_in[10]; p.bk_sar = (const float*)d_in[11];
    p.wv_sar = (const float*)d_in[12]; p.bv_sar = (const float*)d_in[13];
    p.pw_o2s = (const float*)d_in[14]; p.pb_o2s = (const float*)d_in[15];
    p.pw_s2o = (const float*)d_in[16]; p.pb_s2o = (const float*)d_in[17];
    p.gow    = (const float*)d_in[18]; p.gob    = (const float*)d_in[19];
    p.gsw    = (const float*)d_in[20]; p.gsb    = (const float*)d_in[21];
    p.fw     = (const float*)d_in[22]; p.fb     = (const float*)d_in[23];
    p.gma    = (const float*)d_in[24]; p.bta    = (const float*)d_in[25];
    p.mu     = (const float*)d_in[26]; p.var    = (const float*)d_in[27];
    p.out    = (float*)d_out;

    const size_t smem_bytes = SMEM_FLOATS * sizeof(float);  // 203776
    cudaFuncSetAttribute(cmafm_kernel, cudaFuncAttributeMaxDynamicSharedMemorySize,
                         (int)smem_bytes);
    cmafm_kernel<<<4096, TB, smem_bytes>>>(p);
}

// round 5
// speedup vs baseline: 1.9818x; 1.0017x over previous
#include <cuda_runtime.h>
#include <cstdint>

// ---------------------------------------------------------------------------
// CMAFM block, fully fused: one CTA per 8x8 window. 4096 CTAs, 256 thr.
// GEMMs: 4x8 micro-tile over full 64x128 output, k staged in 64-wide halves,
// f32x2 packed FMA accumulation. 5 rotating data buffers + dedicated W stage.
// ---------------------------------------------------------------------------

#define TB 256
using u64 = unsigned long long;

constexpr int CC    = 128;
constexpr int HH    = 256;
constexpr int WWI   = 256;
constexpr int NPIX  = 64;
constexpr int XP    = 132;          // data buffer row pitch (floats)
constexpr int WPI   = 68;           // weight stage pitch (floats)
constexpr int BUF   = NPIX * XP;    // 8448 floats
constexpr int WSTF  = 128 * WPI;    // 8704 floats
constexpr int SMEM_FLOATS = 5 * BUF + WSTF;   // 50944 floats = 203776 B
constexpr size_t NTOT = 4ull * 128 * 256 * 256;

struct P {
    const float *F_opt, *F_sar;
    const float *wq_opt, *bq_opt, *wk_opt, *bk_opt, *wv_opt, *bv_opt;
    const float *wq_sar, *bq_sar, *wk_sar, *bk_sar, *wv_sar, *bv_sar;
    const float *pw_o2s, *pb_o2s, *pw_s2o, *pb_s2o;
    const float *gow, *gob, *gsw, *gsb;
    const float *fw, *fb;
    const float *gma, *bta, *mu, *var;
    float *out;
};

// ---- f32x2 helpers (FFMA2 path; ptxas never emits these from C++) ---------
__device__ __forceinline__ void f2fma(u64& d, u64 a, u64 b) {
    asm("fma.rn.f32x2 %0, %1, %2, %0;" : "+l"(d) : "l"(a), "l"(b));
}
__device__ __forceinline__ u64 f2mul(u64 a, u64 b) {
    u64 d; asm("mul.rn.f32x2 %0, %1, %2;" : "=l"(d) : "l"(a), "l"(b)); return d;
}
__device__ __forceinline__ u64 f2add(u64 a, u64 b) {
    u64 d; asm("add.rn.f32x2 %0, %1, %2;" : "=l"(d) : "l"(a), "l"(b)); return d;
}
__device__ __forceinline__ u64 dup2(float v) {
    u64 d; asm("mov.b64 %0, {%1, %1};" : "=l"(d) : "f"(v)); return d;
}
__device__ __forceinline__ float f2sum(u64 a) {
    float lo, hi; asm("mov.b64 {%0, %1}, %2;" : "=f"(lo), "=f"(hi) : "l"(a));
    return lo + hi;
}

// Load one window (64 px x 128 ch) from NCHW global into smem [n][c].
__device__ __forceinline__ void load_window(float* dst, const float* __restrict__ src,
                                            int gbase, int tid) {
    const int c = tid >> 1, qq = tid & 1;
    const float* s = src + gbase + c * (HH * WWI) + qq * 4;
#pragma unroll
    for (int i = 0; i < 8; ++i) {
        float4 v = *(const float4*)(s + i * WWI);
        float* d = dst + (i * 8 + qq * 4) * XP + c;
        d[0] = v.x; d[XP] = v.y; d[2 * XP] = v.z; d[3 * XP] = v.w;
    }
}

// Transposed store: smem [n][c] -> NCHW global.
__device__ __forceinline__ void store_window(float* __restrict__ g, const float* sbuf,
                                             int gbase, int tid) {
    const int c = tid >> 1, qq = tid & 1;
    float* gp = g + gbase + c * (HH * WWI) + qq * 4;
    const float* sp0 = sbuf + qq * 4 * XP + c;
#pragma unroll
    for (int i = 0; i < 8; ++i) {
        const float* sp = sp0 + i * 8 * XP;
        *(float4*)(gp + i * WWI) = make_float4(sp[0], sp[XP], sp[2 * XP], sp[3 * XP]);
    }
}

// ---------------------------------------------------------------------------
// out[64][128] = [x0 | x1][64][CIN] @ W^T + bias.  W row-major [128][CIN].
// 4x8 per-thread tile (rows rg+16i, cols cg+16j). k in 64-wide staged halves
// with register prefetch of the next half. In-place (outb==x0) is safe.
// ---------------------------------------------------------------------------
__device__ __noinline__ void gemm_core(const float* __restrict__ Wg, int CIN,
                                       const float* __restrict__ bias,
                                       const float* __restrict__ x0,
                                       const float* __restrict__ x1,
                                       float* __restrict__ outb,
                                       float* __restrict__ wst) {
    const int tid = threadIdx.x;
    const int L = tid & 31, w = tid >> 5;
    const int rg = (L & 3) | ((w & 3) << 2);     // 0..15
    const int cg = (L >> 2) | ((w >> 2) << 3);   // 0..15
    const int nh = CIN >> 6;
    const int sc = tid >> 4;                     // stage row base (0..15)
    const int sk = (tid * 4) & 63;               // stage k offset

    u64 acc[4][8];
#pragma unroll
    for (int i = 0; i < 4; ++i)
#pragma unroll
        for (int j = 0; j < 8; ++j) acc[i][j] = 0ull;

    float4 stg[8];
#pragma unroll
    for (int it = 0; it < 8; ++it)
        stg[it] = *(const float4*)(Wg + (sc + it * 16) * CIN + sk);

    for (int h = 0; h < nh; ++h) {
        __syncthreads();  // wst free, prior outputs/readers settled
#pragma unroll
        for (int it = 0; it < 8; ++it)
            *(float4*)(wst + (sc + it * 16) * WPI + sk) = stg[it];
        if (h + 1 < nh) {
            const float* Wn = Wg + (h + 1) * 64;
#pragma unroll
            for (int it = 0; it < 8; ++it)
                stg[it] = *(const float4*)(Wn + (sc + it * 16) * CIN + sk);
        }
        __syncthreads();

        const float* xs = ((h >= 2) ? x1 : x0) + (h & 1) * 64 + rg * XP;
        const float* wr = wst + cg * WPI;
#pragma unroll 2
        for (int ci = 0; ci < 64; ci += 4) {
            ulonglong2 xa0 = *(const ulonglong2*)(xs + ci);
            ulonglong2 xa1 = *(const ulonglong2*)(xs + 16 * XP + ci);
            ulonglong2 xa2 = *(const ulonglong2*)(xs + 32 * XP + ci);
            ulonglong2 xa3 = *(const ulonglong2*)(xs + 48 * XP + ci);
            ulonglong2 wb0 = *(const ulonglong2*)(wr + ci);
            ulonglong2 wb1 = *(const ulonglong2*)(wr + 16 * WPI + ci);
            ulonglong2 wb2 = *(const ulonglong2*)(wr + 32 * WPI + ci);
            ulonglong2 wb3 = *(const ulonglong2*)(wr + 48 * WPI + ci);
            ulonglong2 wb4 = *(const ulonglong2*)(wr + 64 * WPI + ci);
            ulonglong2 wb5 = *(const ulonglong2*)(wr + 80 * WPI + ci);
            ulonglong2 wb6 = *(const ulonglong2*)(wr + 96 * WPI + ci);
            ulonglong2 wb7 = *(const ulonglong2*)(wr + 112 * WPI + ci);
#define ROW(i, xa) \
            f2fma(acc[i][0], xa.x, wb0.x); f2fma(acc[i][0], xa.y, wb0.y); \
            f2fma(acc[i][1], xa.x, wb1.x); f2fma(acc[i][1], xa.y, wb1.y); \
            f2fma(acc[i][2], xa.x, wb2.x); f2fma(acc[i][2], xa.y, wb2.y); \
            f2fma(acc[i][3], xa.x, wb3.x); f2fma(acc[i][3], xa.y, wb3.y); \
            f2fma(acc[i][4], xa.x, wb4.x); f2fma(acc[i][4], xa.y, wb4.y); \
            f2fma(acc[i][5], xa.x, wb5.x); f2fma(acc[i][5], xa.y, wb5.y); \
            f2fma(acc[i][6], xa.x, wb6.x); f2fma(acc[i][6], xa.y, wb6.y); \
            f2fma(acc[i][7], xa.x, wb7.x); f2fma(acc[i][7], xa.y, wb7.y);
            ROW(0, xa0) ROW(1, xa1) ROW(2, xa2) ROW(3, xa3)
#undef ROW
        }
    }
    __syncthreads();  // all reads of x done before (possibly in-place) writes
#pragma unroll
    for (int j = 0; j < 8; ++j) {
        const int cc = cg + 16 * j;
        const float b = __ldg(bias + cc);
#pragma unroll
        for (int i = 0; i < 4; ++i)
            outb[(rg + 16 * i) * XP + cc] = f2sum(acc[i][j]) + b;
    }
    __syncthreads();
}

// ---------------------------------------------------------------------------
// Window attention: 8 warps = 4 heads x 2 row-halves; lane owns one query row.
// Full head_dim = 32 floats = 16 packed f32x2 lanes. Ob may alias Qb.
// ---------------------------------------------------------------------------
__device__ __forceinline__ void attention(const float* __restrict__ Qb,
                                          const float* __restrict__ Kb,
                                          const float* __restrict__ Vb,
                                          float* __restrict__ Ob, int tid) {
    const int L = tid & 31, w = tid >> 5;
    const int head = w >> 1;
    const int row  = (w & 1) * 32 + L;

    u64 q[16];
    {
        const ulonglong2* qp = (const ulonglong2*)(Qb + row * XP + head * 32);
        const u64 sc2 = dup2(0.17677669529663687f);  // 32^-0.5
#pragma unroll
        for (int t = 0; t < 8; ++t) {
            ulonglong2 v = qp[t];
            q[2 * t]     = f2mul(v.x, sc2);
            q[2 * t + 1] = f2mul(v.y, sc2);
        }
    }
    __syncthreads();  // all q loaded before Ob (=Qb) is overwritten

    const float* kbase = Kb + head * 32;
    const float* vbase = Vb + head * 32;

    float m = -1e30f;
#pragma unroll 2
    for (int j = 0; j < 64; ++j) {
        const ulonglong2* kp = (const ulonglong2*)(kbase + j * XP);
        u64 d0 = 0ull, d1 = 0ull, d2 = 0ull, d3 = 0ull;
#pragma unroll
        for (int t = 0; t < 4; ++t) {
            ulonglong2 ka = kp[2 * t], kb = kp[2 * t + 1];
            f2fma(d0, q[4 * t],     ka.x);
            f2fma(d1, q[4 * t + 1], ka.y);
            f2fma(d2, q[4 * t + 2], kb.x);
            f2fma(d3, q[4 * t + 3], kb.y);
        }
        m = fmaxf(m, f2sum(f2add(f2add(d0, d1), f2add(d2, d3))));
    }

    float l = 0.f;
    u64 o[16];
#pragma unroll
    for (int t = 0; t < 16; ++t) o[t] = 0ull;

    for (int j = 0; j < 64; ++j) {
        const ulonglong2* kp = (const ulonglong2*)(kbase + j * XP);
        u64 d0 = 0ull, d1 = 0ull, d2 = 0ull, d3 = 0ull;
#pragma unroll
        for (int t = 0; t < 4; ++t) {
            ulonglong2 ka = kp[2 * t], kb = kp[2 * t + 1];
            f2fma(d0, q[4 * t],     ka.x);
            f2fma(d1, q[4 * t + 1], ka.y);
            f2fma(d2, q[4 * t + 2], kb.x);
            f2fma(d3, q[4 * t + 3], kb.y);
        }
        const float e = __expf(f2sum(f2add(f2add(d0, d1), f2add(d2, d3))) - m);
        l += e;
        const u64 ee = dup2(e);
        const ulonglong2* vp = (const ulonglong2*)(vbase + j * XP);
#pragma unroll
        for (int t = 0; t < 8; ++t) {
            ulonglong2 v2 = vp[t];
            f2fma(o[2 * t],     ee, v2.x);
            f2fma(o[2 * t + 1], ee, v2.y);
        }
    }
    const u64 inv2 = dup2(1.f / l);
    ulonglong2* op = (ulonglong2*)(Ob + row * XP + head * 32);
#pragma unroll
    for (int t = 0; t < 8; ++t) {
        ulonglong2 r;
        r.x = f2mul(o[2 * t], inv2);
        r.y = f2mul(o[2 * t + 1], inv2);
        op[t] = r;
    }
    __syncthreads();
}

__device__ __forceinline__ float sigmoidf_(float x) {
    return 1.f / (1.f + __expf(-x));
}

extern __shared__ float smem[];

__global__ void __launch_bounds__(TB, 1) cmafm_kernel(P p) {
    float* B0 = smem;
    float* B1 = smem + BUF;
    float* B2 = smem + 2 * BUF;
    float* B3 = smem + 3 * BUF;
    float* B4 = smem + 4 * BUF;
    float* WST = smem + 5 * BUF;

    const int tid  = threadIdx.x;
    const int widx = blockIdx.x;
    const int b  = widx >> 10;
    const int wh = (widx >> 5) & 31;
    const int ww = widx & 31;
    const int gbase = b * (CC * HH * WWI) + (wh * 8) * WWI + ww * 8;

    load_window(B0, p.F_opt, gbase, tid);
    load_window(B1, p.F_sar, gbase, tid);

    // --- direction opt->sar ---
    gemm_core(p.wq_opt, 128, p.bq_opt, B0, nullptr, B2, WST);   // Qo
    gemm_core(p.wk_sar, 128, p.bk_sar, B1, nullptr, B3, WST);   // Ks
    gemm_core(p.wv_sar, 128, p.bv_sar, B1, nullptr, B4, WST);   // Vs
    attention(B2, B3, B4, B2, tid);
    gemm_core(p.pw_o2s, 128, p.pb_o2s, B2, nullptr, B3, WST);   // F_o2s -> B3

    // --- direction sar->opt ---
    gemm_core(p.wq_sar, 128, p.bq_sar, B1, nullptr, B2, WST);   // Qs
    gemm_core(p.wk_opt, 128, p.bk_opt, B0, nullptr, B4, WST);   // Ko
    gemm_core(p.wv_opt, 128, p.bv_opt, B0, nullptr, B0, WST);   // Vo (in-place)
    attention(B2, B4, B0, B2, tid);
    load_window(B0, p.F_opt, gbase, tid);                       // reload F_opt
    gemm_core(p.pw_s2o, 128, p.pb_s2o, B2, nullptr, B4, WST);   // F_s2o -> B4

    // --- gate opt: sigma = sigmoid(Wg @ [F_opt ; F_o2s]) ---
    gemm_core(p.gow, 256, p.gob, B0, B3, B2, WST);
    for (int idx = tid; idx < NPIX * CC; idx += TB) {
        const int off = (idx >> 7) * XP + (idx & 127);
        const float s = sigmoidf_(B2[off]);
        B2[off] = s;
        B3[off] = B0[off] + s * B3[off];       // F_opt_new
    }
    __syncthreads();
    store_window(p.out + NTOT, B2, gbase, tid);      // sigma_opt

    // --- gate sar ---
    gemm_core(p.gsw, 256, p.gsb, B1, B4, B0, WST);   // leading sync orders above
    for (int idx = tid; idx < NPIX * CC; idx += TB) {
        const int off = (idx >> 7) * XP + (idx & 127);
        const float s = sigmoidf_(B0[off]);
        B0[off] = s;
        B4[off] = B1[off] + s * B4[off];       // F_sar_new
    }
    __syncthreads();
    store_window(p.out + 2 * NTOT, B0, gbase, tid);  // sigma_sar

    // --- fuse + BN + SiLU ---
    gemm_core(p.fw, 256, p.fb, B3, B4, B2, WST);
    {
        const int c = tid >> 1, qq = tid & 1;
        const float inv = p.gma[c] * rsqrtf(p.var[c] + 1e-5f);
        const float sh  = p.bta[c] - p.mu[c] * inv;
        float* g = p.out + gbase + c * (HH * WWI) + qq * 4;
        const float* sp0 = B2 + qq * 4 * XP + c;
#pragma unroll
        for (int i = 0; i < 8; ++i) {
            const float* sp = sp0 + i * 8 * XP;
            float y0 = sp[0]      * inv + sh;
            float y1 = sp[XP]     * inv + sh;
            float y2 = sp[2 * XP] * inv + sh;
            float y3 = sp[3 * XP] * inv + sh;
            y0 *= sigmoidf_(y0); y1 *= sigmoidf_(y1);
            y2 *= sigmoidf_(y2); y3 *= sigmoidf_(y3);
            *(float4*)(g + i * WWI) = make_float4(y0, y1, y2, y3);
        }
    }
}

extern "C" void kernel_launch(void* const* d_in, const int* in_sizes, int n_in,
                              void* d_out, int out_size) {
    (void)in_sizes; (void)n_in; (void)out_size;
    P p;
    p.F_opt  = (const float*)d_in[0];  p.F_sar  = (const float*)d_in[1];
    p.wq_opt = (const float*)d_in[2];  p.bq_opt = (const float*)d_in[3];
    p.wk_opt = (const float*)d_in[4];  p.bk_opt = (const float*)d_in[5];
    p.wv_opt = (const float*)d_in[6];  p.bv_opt = (const float*)d_in[7];
    p.wq_sar = (const float*)d_in[8];  p.bq_sar = (const float*)d_in[9];
    p.wk_sar = (const float*)d_in[10]; p.bk_sar = (const float*)d_in[11];
    p.wv_sar = (const float*)d_in[12]; p.bv_sar = (const float*)d_in[13];
    p.pw_o2s = (const float*)d_in[14]; p.pb_o2s = (const float*)d_in[15];
    p.pw_s2o = (const float*)d_in[16]; p.pb_s2o = (const float*)d_in[17];
    p.gow    = (const float*)d_in[18]; p.gob    = (const float*)d_in[19];
    p.gsw    = (const float*)d_in[20]; p.gsb    = (const float*)d_in[21];
    p.fw     = (const float*)d_in[22]; p.fb     = (const float*)d_in[23];
    p.gma    = (const float*)d_in[24]; p.bta    = (const float*)d_in[25];
    p.mu     = (const float*)d_in[26]; p.var    = (const float*)d_in[27];
    p.out    = (float*)d_out;

    const size_t smem_bytes = SMEM_FLOATS * sizeof(float);  // 203776
    cudaFuncSetAttribute(cmafm_kernel, cudaFuncAttributeMaxDynamicSharedMemorySize,
                         (int)smem_bytes);
    cmafm_kernel<<<4096, TB, smem_bytes>>>(p);
}